// round 10
// baseline (speedup 1.0000x reference)
#include <cuda_runtime.h>
#include <cuda_bf16.h>
#include <math.h>
#include <stdint.h>

#define NN 8192
#define FIN 256
#define DD 128
#define ALPHA 0.2f
#define SPLITS 16
#define BM 128
#define BN 64
#define TILES ((NN / SPLITS) / BN)   // 8

// Scratch (allocation-free rule: __device__ globals).
// Packed bf16x2 hi/lo planes. 16 uint4 per row = 64 words = 128 bf16.
__device__ uint4 gHh[(size_t)NN * 16];
__device__ uint4 gHl[(size_t)NN * 16];
__device__ uint4 gKh[(size_t)NN * 16];
__device__ uint4 gKl[(size_t)NN * 16];
__device__ uint4 gVh[(size_t)NN * 16];
__device__ uint4 gVl[(size_t)NN * 16];
// inp split planes: 8192 x 256 -> 128 words/row.
__device__ uint4 gIh[(size_t)NN * 32];
__device__ uint4 gIl[(size_t)NN * 32];
// W split planes: 3 mats x 256 rows x 64 words.
__device__ uint4 gWh[3 * 256 * 16];
__device__ uint4 gWl[3 * 256 * 16];
__device__ float gNum[(size_t)SPLITS * NN * DD];
__device__ float gDen[(size_t)SPLITS * NN];

// ---------------------------------------------------------------------------
// helpers
// ---------------------------------------------------------------------------
__device__ __forceinline__ uint32_t smem_u32(const void* p) {
  uint32_t a;
  asm("{ .reg .u64 t; cvta.to.shared.u64 t, %1; cvt.u32.u64 %0, t; }"
      : "=r"(a) : "l"(p));
  return a;
}
__device__ __forceinline__ uint32_t pack_bf(float a, float b) {
  __nv_bfloat162 r = __floats2bfloat162_rn(a, b);
  return *reinterpret_cast<uint32_t*>(&r);
}

#define LDSM_X4(r0, r1, r2, r3, a)                                            \
  asm volatile("ldmatrix.sync.aligned.m8n8.x4.shared.b16 {%0,%1,%2,%3}, [%4];"\
               : "=r"(r0), "=r"(r1), "=r"(r2), "=r"(r3) : "r"(a))
#define LDSM_X4T(r0, r1, r2, r3, a)                                           \
  asm volatile("ldmatrix.sync.aligned.m8n8.x4.trans.shared.b16 {%0,%1,%2,%3}, [%4];" \
               : "=r"(r0), "=r"(r1), "=r"(r2), "=r"(r3) : "r"(a))

__device__ __forceinline__ void mma_bf16(float* d, const uint32_t* a,
                                         uint32_t b0, uint32_t b1) {
  asm volatile(
      "mma.sync.aligned.m16n8k16.row.col.f32.bf16.bf16.f32 "
      "{%0,%1,%2,%3}, {%4,%5,%6,%7}, {%8,%9}, {%0,%1,%2,%3};"
      : "+f"(d[0]), "+f"(d[1]), "+f"(d[2]), "+f"(d[3])
      : "r"(a[0]), "r"(a[1]), "r"(a[2]), "r"(a[3]), "r"(b0), "r"(b1));
}

__device__ __forceinline__ void cp16(uint32_t dst, const void* src) {
  asm volatile("cp.async.cg.shared.global [%0], [%1], 16;" :: "r"(dst), "l"(src));
}
#define CP_COMMIT() asm volatile("cp.async.commit_group;" ::: "memory")
#define CP_WAIT1()  asm volatile("cp.async.wait_group 1;" ::: "memory")

// ---------------------------------------------------------------------------
// Kernel 0: split fp32 inputs into packed bf16 hi/lo planes.
// words 0..1048575: inp; words 1048576..: W (3 x 16384 words).
// ---------------------------------------------------------------------------
__global__ __launch_bounds__(256) void split_kernel(
    const float* __restrict__ inp, const float* __restrict__ W0,
    const float* __restrict__ W1, const float* __restrict__ W2) {
  int idx = blockIdx.x * 256 + threadIdx.x;
  const float* src;
  uint32_t* dh;
  uint32_t* dl;
  int off;
  if (idx < 1048576) {
    src = inp; off = idx;
    dh = (uint32_t*)gIh; dl = (uint32_t*)gIl;
  } else {
    int j = idx - 1048576;             // 0..49151
    int mat = j / 16384;
    off = j % 16384;
    src = (mat == 0) ? W0 : (mat == 1) ? W1 : W2;
    dh = (uint32_t*)gWh + mat * 16384;
    dl = (uint32_t*)gWl + mat * 16384;
  }
  float2 v = *(const float2*)(src + 2 * (size_t)off);
  float h0 = __bfloat162float(__float2bfloat16(v.x));
  float h1 = __bfloat162float(__float2bfloat16(v.y));
  dh[off] = pack_bf(h0, h1);
  dl[off] = pack_bf(v.x - h0, v.y - h1);
}

// ---------------------------------------------------------------------------
// Kernel A: projections via warp mma.sync bf16 hi/lo (3-term).
// CTA = 64 rows x 128 cols, 128 threads (4 warps, 16 rows each), K chunks of 32.
// Stage layout: Ahi 0 (64x80B), Alo 5120, Bhi 10240 (32x272B), Blo 18944.
// ---------------------------------------------------------------------------
#define PSTG 27648
#define PSMEM 55296
__global__ void __launch_bounds__(128, 1) proj_kernel() {
  extern __shared__ char smem[];
  uint32_t sb = smem_u32(smem);
  int t = threadIdx.x, w = t >> 5, lane = t & 31;
  int g = lane >> 2, tig = lane & 3;
  int q = lane >> 3, r = lane & 7;
  int rowbase = blockIdx.x * 64;
  int mat = blockIdx.y;
  const uint4* Wh = gWh + mat * 256 * 16;
  const uint4* Wl = gWl + mat * 256 * 16;
  uint32_t* Ph = (uint32_t*)((mat == 0) ? gHh : (mat == 1) ? gKh : gVh);
  uint32_t* Pl = (uint32_t*)((mat == 0) ? gHl : (mat == 1) ? gKl : gVl);

  uint32_t offA = (uint32_t)((w * 16 + (q & 1) * 8 + r) * 80 + (q >> 1) * 16);
  uint32_t offB = (uint32_t)(10240 + ((q & 1) * 8 + r) * 272 + (q >> 1) * 16);

  // async chunk loader: 12 cp16 per thread per chunk
  auto load_chunk = [&](int s, int c) {
    uint32_t base = sb + (uint32_t)(s * PSTG);
    // A planes: 64 rows x 4 uint4 x 2 planes = 512 cp16
#pragma unroll
    for (int i = 0; i < 4; i++) {
      int idx = t + i * 128;                  // 0..511
      int plane = idx >> 8, row = (idx >> 2) & 63, ch = idx & 3;
      const uint4* srcp = (plane ? gIl : gIh) + (size_t)(rowbase + row) * 32 + c * 4 + ch;
      cp16(base + plane * 5120 + row * 80 + ch * 16, srcp);
    }
    // B planes: 32 rows x 16 uint4 x 2 planes = 1024 cp16
#pragma unroll
    for (int i = 0; i < 8; i++) {
      int idx = t + i * 128;                  // 0..1023
      int plane = idx >> 9, row = (idx >> 4) & 31, ch = idx & 15;
      const uint4* srcp = (plane ? Wl : Wh) + (size_t)(c * 32 + row) * 16 + ch;
      cp16(base + 10240 + plane * 8704 + row * 272 + ch * 16, srcp);
    }
  };

  load_chunk(0, 0); CP_COMMIT();
  load_chunk(1, 1); CP_COMMIT();

  float oacc[16][4];
#pragma unroll
  for (int c = 0; c < 16; c++)
#pragma unroll
    for (int k = 0; k < 4; k++) oacc[c][k] = 0.f;

  for (int c = 0; c < 8; c++) {
    int s = c & 1;
    CP_WAIT1();
    __syncthreads();
    uint32_t aA = sb + (uint32_t)(s * PSTG) + offA;
    uint32_t aB = sb + (uint32_t)(s * PSTG) + offB;
#pragma unroll
    for (int kk = 0; kk < 2; kk++) {
      uint32_t ah[4], al[4];
      LDSM_X4(ah[0], ah[1], ah[2], ah[3], aA + kk * 32);
      LDSM_X4(al[0], al[1], al[2], al[3], aA + 5120 + kk * 32);
#pragma unroll
      for (int np = 0; np < 8; np++) {
        uint32_t bh[4], bl[4];
        uint32_t boff = (uint32_t)(kk * 4352 + np * 32);
        LDSM_X4T(bh[0], bh[1], bh[2], bh[3], aB + boff);
        LDSM_X4T(bl[0], bl[1], bl[2], bl[3], aB + 8704 + boff);
        mma_bf16(oacc[2 * np], ah, bh[0], bh[1]);
        mma_bf16(oacc[2 * np], ah, bl[0], bl[1]);
        mma_bf16(oacc[2 * np], al, bh[0], bh[1]);
        mma_bf16(oacc[2 * np + 1], ah, bh[2], bh[3]);
        mma_bf16(oacc[2 * np + 1], ah, bl[2], bl[3]);
        mma_bf16(oacc[2 * np + 1], al, bh[2], bh[3]);
      }
    }
    __syncthreads();
    if (c + 2 < 8) load_chunk(s, c + 2);
    CP_COMMIT();
  }

  // epilogue: split fragments to hi/lo packed words
  size_t row0 = (size_t)(rowbase + w * 16 + g) * 64;
  size_t row8 = row0 + 8 * 64;
#pragma unroll
  for (int np = 0; np < 8; np++) {
#pragma unroll
    for (int half = 0; half < 2; half++) {
      float* d = oacc[2 * np + half];
      int word = np * 8 + half * 4 + tig;
      float h0 = __bfloat162float(__float2bfloat16(d[0]));
      float h1 = __bfloat162float(__float2bfloat16(d[1]));
      float h2 = __bfloat162float(__float2bfloat16(d[2]));
      float h3 = __bfloat162float(__float2bfloat16(d[3]));
      Ph[row0 + word] = pack_bf(h0, h1);
      Pl[row0 + word] = pack_bf(d[0] - h0, d[1] - h1);
      Ph[row8 + word] = pack_bf(h2, h3);
      Pl[row8 + word] = pack_bf(d[2] - h2, d[3] - h3);
    }
  }
}

// ---------------------------------------------------------------------------
// Kernel B: fused attention. H fragments in registers (LDG prologue),
// 3-stage cp.async KV buffer, one __syncthreads per tile.
// Stage: Khi 0 / Klo 17408 / Vhi 34816 / Vlo 52224; 64 rows, stride 272.
// ---------------------------------------------------------------------------
#define TRS 272
#define STAGE 69632
#define SMEM_BYTES 208896           // 3 stages

__device__ __forceinline__ void load_kv_async(uint32_t sb, int s, int cb, int t) {
#pragma unroll
  for (int i = 0; i < 16; i++) {
    int idx = t + i * 256;                 // 0..4095
    int sec = idx >> 10, row = (idx >> 4) & 63, ch = idx & 15;
    const uint4* base = (sec == 0) ? gKh : (sec == 1) ? gKl : (sec == 2) ? gVh : gVl;
    cp16(sb + s * STAGE + sec * 17408 + row * TRS + ch * 16,
         base + (size_t)(cb + row) * 16 + ch);
  }
}

__global__ void __launch_bounds__(256, 1) attn_kernel(const int* __restrict__ adj) {
  extern __shared__ char smem[];
  uint32_t sb = smem_u32(smem);
  int t = threadIdx.x, w = t >> 5, lane = t & 31;
  int g = lane >> 2, tig = lane & 3;
  int rowbase = blockIdx.x * BM;
  int colstart = blockIdx.y * (NN / SPLITS);
  int q = lane >> 3, r = lane & 7;
  uint32_t offB = (uint32_t)(((q >> 1) * 8 + r) * TRS + (q & 1) * 16);
  uint32_t offV = (uint32_t)(34816 + ((q & 1) * 8 + r) * TRS + (q >> 1) * 16);

  // first two KV stages in flight
  load_kv_async(sb, 0, colstart, t);
  CP_COMMIT();
  load_kv_async(sb, 1, colstart + BN, t);
  CP_COMMIT();

  // H fragments via direct LDG (A-fragment layout == packed word layout)
  uint32_t ahf[8][4], alf[8][4];
  {
    const uint32_t* Hh = (const uint32_t*)gHh;
    const uint32_t* Hl = (const uint32_t*)gHl;
    size_t b0 = (size_t)(rowbase + w * 16 + g) * 64;
    size_t b8 = b0 + 8 * 64;
#pragma unroll
    for (int kk = 0; kk < 8; kk++) {
      int wd = kk * 8 + tig;
      ahf[kk][0] = Hh[b0 + wd];     ahf[kk][1] = Hh[b8 + wd];
      ahf[kk][2] = Hh[b0 + wd + 4]; ahf[kk][3] = Hh[b8 + wd + 4];
      alf[kk][0] = Hl[b0 + wd];     alf[kk][1] = Hl[b8 + wd];
      alf[kk][2] = Hl[b0 + wd + 4]; alf[kk][3] = Hl[b8 + wd + 4];
    }
  }

  float oacc[16][4];
#pragma unroll
  for (int c = 0; c < 16; c++)
#pragma unroll
    for (int k = 0; k < 4; k++) oacc[c][k] = 0.f;
  float den0 = 0.f, den1 = 0.f;

  const int* arow0 = adj + (size_t)(rowbase + w * 16 + g) * NN;
  const int* arow1 = arow0 + (size_t)8 * NN;

  int s3 = 0;
  for (int tt = 0; tt < TILES; tt++) {
    int cb = colstart + tt * BN;
    CP_WAIT1();
    __syncthreads();                        // L(tt) visible; stage (tt+2)%3 free
    if (tt + 2 < TILES) load_kv_async(sb, (tt + 2) % 3, colstart + (tt + 2) * BN, t);
    CP_COMMIT();

    // adj prefetch (hidden under S MMAs)
    int2 am[16];
#pragma unroll
    for (int n = 0; n < 8; n++) {
      am[n] = *(const int2*)(arow0 + cb + n * 8 + 2 * tig);
      am[n + 8] = *(const int2*)(arow1 + cb + n * 8 + 2 * tig);
    }

    uint32_t aBh = sb + (uint32_t)(s3 * STAGE) + offB;
    uint32_t aVh = sb + (uint32_t)(s3 * STAGE) + offV;

    // ---- S = H @ K^T (hi/lo: hh + hl + lh), A from registers ----
    float sacc[8][4];
#pragma unroll
    for (int c = 0; c < 8; c++)
#pragma unroll
      for (int k = 0; k < 4; k++) sacc[c][k] = 0.f;

#pragma unroll
    for (int kk = 0; kk < 8; kk++) {
#pragma unroll
      for (int np = 0; np < 4; np++) {
        uint32_t bh[4], bl[4];
        uint32_t boff = (uint32_t)(np * (16 * TRS) + kk * 32);
        LDSM_X4(bh[0], bh[1], bh[2], bh[3], aBh + boff);
        LDSM_X4(bl[0], bl[1], bl[2], bl[3], aBh + 17408 + boff);
        mma_bf16(sacc[2 * np], ahf[kk], bh[0], bh[1]);
        mma_bf16(sacc[2 * np], ahf[kk], bl[0], bl[1]);
        mma_bf16(sacc[2 * np], alf[kk], bh[0], bh[1]);
        mma_bf16(sacc[2 * np + 1], ahf[kk], bh[2], bh[3]);
        mma_bf16(sacc[2 * np + 1], ahf[kk], bl[2], bl[3]);
        mma_bf16(sacc[2 * np + 1], alf[kk], bh[2], bh[3]);
      }
    }

    // ---- leakyrelu + adj mask + exp -> P fragments -> PV ----
#pragma unroll
    for (int kk = 0; kk < 4; kk++) {
      uint32_t phi[4], plo[4];
#pragma unroll
      for (int cp = 0; cp < 2; cp++) {
        int n = 2 * kk + cp;
        int2 m0 = am[n];
        int2 m1 = am[n + 8];
        float e0 = sacc[n][0], e1 = sacc[n][1], e2 = sacc[n][2], e3 = sacc[n][3];
        e0 = e0 > 0.f ? e0 : ALPHA * e0;
        e1 = e1 > 0.f ? e1 : ALPHA * e1;
        e2 = e2 > 0.f ? e2 : ALPHA * e2;
        e3 = e3 > 0.f ? e3 : ALPHA * e3;
        float p0 = (m0.x > 0) ? __expf(e0) : 0.f;
        float p1 = (m0.y > 0) ? __expf(e1) : 0.f;
        float p2 = (m1.x > 0) ? __expf(e2) : 0.f;
        float p3 = (m1.y > 0) ? __expf(e3) : 0.f;
        den0 += p0 + p1;
        den1 += p2 + p3;
        float h0 = __bfloat162float(__float2bfloat16(p0));
        float h1 = __bfloat162float(__float2bfloat16(p1));
        float h2 = __bfloat162float(__float2bfloat16(p2));
        float h3 = __bfloat162float(__float2bfloat16(p3));
        phi[2 * cp + 0] = pack_bf(h0, h1);
        phi[2 * cp + 1] = pack_bf(h2, h3);
        plo[2 * cp + 0] = pack_bf(p0 - h0, p1 - h1);
        plo[2 * cp + 1] = pack_bf(p2 - h2, p3 - h3);
      }
#pragma unroll
      for (int cp = 0; cp < 8; cp++) {
        uint32_t vh[4], vl[4];
        uint32_t voff = (uint32_t)(kk * (16 * TRS) + cp * 32);
        LDSM_X4T(vh[0], vh[1], vh[2], vh[3], aVh + voff);
        LDSM_X4T(vl[0], vl[1], vl[2], vl[3], aVh + 17408 + voff);
        mma_bf16(oacc[2 * cp], phi, vh[0], vh[1]);
        mma_bf16(oacc[2 * cp], phi, vl[0], vl[1]);
        mma_bf16(oacc[2 * cp], plo, vh[0], vh[1]);
        mma_bf16(oacc[2 * cp + 1], phi, vh[2], vh[3]);
        mma_bf16(oacc[2 * cp + 1], phi, vl[2], vl[3]);
        mma_bf16(oacc[2 * cp + 1], plo, vh[2], vh[3]);
      }
    }
    s3 = (s3 == 2) ? 0 : s3 + 1;
  }

  // ---- epilogue: den (quad reduce) + O partials ----
  den0 += __shfl_xor_sync(0xffffffffu, den0, 1);
  den0 += __shfl_xor_sync(0xffffffffu, den0, 2);
  den1 += __shfl_xor_sync(0xffffffffu, den1, 1);
  den1 += __shfl_xor_sync(0xffffffffu, den1, 2);
  if (tig == 0) {
    gDen[(size_t)blockIdx.y * NN + rowbase + w * 16 + g] = den0;
    gDen[(size_t)blockIdx.y * NN + rowbase + w * 16 + g + 8] = den1;
  }
  float* base0 = gNum + ((size_t)blockIdx.y * NN + rowbase + w * 16 + g) * DD;
  float* base1 = base0 + (size_t)8 * DD;
#pragma unroll
  for (int c = 0; c < 16; c++) {
    *(float2*)(base0 + c * 8 + 2 * tig) = make_float2(oacc[c][0], oacc[c][1]);
    *(float2*)(base1 + c * 8 + 2 * tig) = make_float2(oacc[c][2], oacc[c][3]);
  }
}

// ---------------------------------------------------------------------------
// Kernel C: combine split partials, divide, ELU (float4 vectorized).
// ---------------------------------------------------------------------------
__global__ __launch_bounds__(256) void reduce_kernel(float* __restrict__ out) {
  int idx = blockIdx.x * 256 + threadIdx.x;   // over N*D/4 = 262144
  int row = idx >> 5;
  int c4 = (idx & 31) * 4;
  float4 num = make_float4(0.f, 0.f, 0.f, 0.f);
  float den = 0.f;
#pragma unroll
  for (int s = 0; s < SPLITS; s++) {
    float4 v = *(const float4*)(gNum + ((size_t)s * NN + row) * DD + c4);
    num.x += v.x; num.y += v.y; num.z += v.z; num.w += v.w;
    den += gDen[(size_t)s * NN + row];
  }
  float inv = 1.f / den;
  float h0 = num.x * inv, h1 = num.y * inv, h2 = num.z * inv, h3 = num.w * inv;
  float4 o;
  o.x = (h0 > 0.f) ? h0 : expm1f(h0);
  o.y = (h1 > 0.f) ? h1 : expm1f(h1);
  o.z = (h2 > 0.f) ? h2 : expm1f(h2);
  o.w = (h3 > 0.f) ? h3 : expm1f(h3);
  *(float4*)(out + (size_t)row * DD + c4) = o;
}

// ---------------------------------------------------------------------------
extern "C" void kernel_launch(void* const* d_in, const int* in_sizes, int n_in,
                              void* d_out, int out_size) {
  const float* inp = (const float*)d_in[0];
  const int* adj = (const int*)d_in[1];
  const float* W = (const float*)d_in[2];
  const float* W2 = (const float*)d_in[3];
  const float* W3 = (const float*)d_in[4];
  float* out = (float*)d_out;

  split_kernel<<<4288, 256>>>(inp, W, W2, W3);

  cudaFuncSetAttribute(proj_kernel, cudaFuncAttributeMaxDynamicSharedMemorySize,
                       PSMEM);
  proj_kernel<<<dim3(NN / 64, 3), 128, PSMEM>>>();

  cudaFuncSetAttribute(attn_kernel, cudaFuncAttributeMaxDynamicSharedMemorySize,
                       SMEM_BYTES);
  attn_kernel<<<dim3(NN / BM, SPLITS), 256, SMEM_BYTES>>>(adj);

  reduce_kernel<<<(NN * DD) / 1024, 256>>>(out);
}

// round 11
// speedup vs baseline: 1.4316x; 1.4316x over previous
#include <cuda_runtime.h>
#include <cuda_bf16.h>
#include <math.h>
#include <stdint.h>

#define NN 8192
#define FIN 256
#define DD 128
#define ALPHA 0.2f
#define SPLITS 16
#define BM 128
#define BN 64
#define TILES ((NN / SPLITS) / BN)   // 8

// Scratch (allocation-free rule: __device__ globals).
// Packed bf16x2 hi/lo planes. 16 uint4 per row = 64 words = 128 bf16.
__device__ uint4 gHh[(size_t)NN * 16];
__device__ uint4 gHl[(size_t)NN * 16];
__device__ uint4 gKh[(size_t)NN * 16];
__device__ uint4 gKl[(size_t)NN * 16];
__device__ uint4 gVh[(size_t)NN * 16];
__device__ uint4 gVl[(size_t)NN * 16];
// inp split planes: 8192 x 256 -> 128 words/row.
__device__ uint4 gIh[(size_t)NN * 32];
__device__ uint4 gIl[(size_t)NN * 32];
// W split planes: 3 mats x 256 rows x 64 words.
__device__ uint4 gWh[3 * 256 * 16];
__device__ uint4 gWl[3 * 256 * 16];
__device__ float gNum[(size_t)SPLITS * NN * DD];
__device__ float gDen[(size_t)SPLITS * NN];

// ---------------------------------------------------------------------------
// helpers
// ---------------------------------------------------------------------------
__device__ __forceinline__ uint32_t smem_u32(const void* p) {
  uint32_t a;
  asm("{ .reg .u64 t; cvta.to.shared.u64 t, %1; cvt.u32.u64 %0, t; }"
      : "=r"(a) : "l"(p));
  return a;
}
__device__ __forceinline__ uint32_t pack_bf(float a, float b) {
  __nv_bfloat162 r = __floats2bfloat162_rn(a, b);
  return *reinterpret_cast<uint32_t*>(&r);
}

#define LDSM_X4(r0, r1, r2, r3, a)                                            \
  asm volatile("ldmatrix.sync.aligned.m8n8.x4.shared.b16 {%0,%1,%2,%3}, [%4];"\
               : "=r"(r0), "=r"(r1), "=r"(r2), "=r"(r3) : "r"(a))
#define LDSM_X4T(r0, r1, r2, r3, a)                                           \
  asm volatile("ldmatrix.sync.aligned.m8n8.x4.trans.shared.b16 {%0,%1,%2,%3}, [%4];" \
               : "=r"(r0), "=r"(r1), "=r"(r2), "=r"(r3) : "r"(a))

__device__ __forceinline__ void mma_bf16(float* d, const uint32_t* a,
                                         uint32_t b0, uint32_t b1) {
  asm volatile(
      "mma.sync.aligned.m16n8k16.row.col.f32.bf16.bf16.f32 "
      "{%0,%1,%2,%3}, {%4,%5,%6,%7}, {%8,%9}, {%0,%1,%2,%3};"
      : "+f"(d[0]), "+f"(d[1]), "+f"(d[2]), "+f"(d[3])
      : "r"(a[0]), "r"(a[1]), "r"(a[2]), "r"(a[3]), "r"(b0), "r"(b1));
}

__device__ __forceinline__ void cp16(uint32_t dst, const void* src) {
  asm volatile("cp.async.cg.shared.global [%0], [%1], 16;" :: "r"(dst), "l"(src));
}
#define CP_COMMIT() asm volatile("cp.async.commit_group;" ::: "memory")
#define CP_WAIT1()  asm volatile("cp.async.wait_group 1;" ::: "memory")

// ---------------------------------------------------------------------------
// Kernel 0: split fp32 inputs into packed bf16 hi/lo planes.
// words 0..1048575: inp; words 1048576..: W (3 x 16384 words).
// ---------------------------------------------------------------------------
__global__ __launch_bounds__(256) void split_kernel(
    const float* __restrict__ inp, const float* __restrict__ W0,
    const float* __restrict__ W1, const float* __restrict__ W2) {
  int idx = blockIdx.x * 256 + threadIdx.x;
  const float* src;
  uint32_t* dh;
  uint32_t* dl;
  int off;
  if (idx < 1048576) {
    src = inp; off = idx;
    dh = (uint32_t*)gIh; dl = (uint32_t*)gIl;
  } else {
    int j = idx - 1048576;             // 0..49151
    int mat = j / 16384;
    off = j % 16384;
    src = (mat == 0) ? W0 : (mat == 1) ? W1 : W2;
    dh = (uint32_t*)gWh + mat * 16384;
    dl = (uint32_t*)gWl + mat * 16384;
  }
  float2 v = *(const float2*)(src + 2 * (size_t)off);
  float h0 = __bfloat162float(__float2bfloat16(v.x));
  float h1 = __bfloat162float(__float2bfloat16(v.y));
  dh[off] = pack_bf(h0, h1);
  dl[off] = pack_bf(v.x - h0, v.y - h1);
}

// ---------------------------------------------------------------------------
// Kernel A: projections via warp mma.sync bf16 hi/lo (3-term).
// CTA = 64 rows x 128 cols, 128 threads (4 warps, 16 rows each), K chunks of 32.
// Stage layout: Ahi 0 (64x80B), Alo 5120, Bhi 10240 (32x272B), Blo 18944.
// ---------------------------------------------------------------------------
#define PSTG 27648
#define PSMEM 55296
__global__ void __launch_bounds__(128, 1) proj_kernel() {
  extern __shared__ char smem[];
  uint32_t sb = smem_u32(smem);
  int t = threadIdx.x, w = t >> 5, lane = t & 31;
  int g = lane >> 2, tig = lane & 3;
  int q = lane >> 3, r = lane & 7;
  int rowbase = blockIdx.x * 64;
  int mat = blockIdx.y;
  const uint4* Wh = gWh + mat * 256 * 16;
  const uint4* Wl = gWl + mat * 256 * 16;
  uint32_t* Ph = (uint32_t*)((mat == 0) ? gHh : (mat == 1) ? gKh : gVh);
  uint32_t* Pl = (uint32_t*)((mat == 0) ? gHl : (mat == 1) ? gKl : gVl);

  uint32_t offA = (uint32_t)((w * 16 + (q & 1) * 8 + r) * 80 + (q >> 1) * 16);
  uint32_t offB = (uint32_t)(10240 + ((q & 1) * 8 + r) * 272 + (q >> 1) * 16);

  // async chunk loader: 12 cp16 per thread per chunk
  auto load_chunk = [&](int s, int c) {
    uint32_t base = sb + (uint32_t)(s * PSTG);
    // A planes: 64 rows x 4 uint4 x 2 planes = 512 cp16
#pragma unroll
    for (int i = 0; i < 4; i++) {
      int idx = t + i * 128;                  // 0..511
      int plane = idx >> 8, row = (idx >> 2) & 63, ch = idx & 3;
      const uint4* srcp = (plane ? gIl : gIh) + (size_t)(rowbase + row) * 32 + c * 4 + ch;
      cp16(base + plane * 5120 + row * 80 + ch * 16, srcp);
    }
    // B planes: 32 rows x 16 uint4 x 2 planes = 1024 cp16
#pragma unroll
    for (int i = 0; i < 8; i++) {
      int idx = t + i * 128;                  // 0..1023
      int plane = idx >> 9, row = (idx >> 4) & 31, ch = idx & 15;
      const uint4* srcp = (plane ? Wl : Wh) + (size_t)(c * 32 + row) * 16 + ch;
      cp16(base + 10240 + plane * 8704 + row * 272 + ch * 16, srcp);
    }
  };

  load_chunk(0, 0); CP_COMMIT();
  load_chunk(1, 1); CP_COMMIT();

  float oacc[16][4];
#pragma unroll
  for (int c = 0; c < 16; c++)
#pragma unroll
    for (int k = 0; k < 4; k++) oacc[c][k] = 0.f;

  for (int c = 0; c < 8; c++) {
    int s = c & 1;
    CP_WAIT1();
    __syncthreads();
    uint32_t aA = sb + (uint32_t)(s * PSTG) + offA;
    uint32_t aB = sb + (uint32_t)(s * PSTG) + offB;
#pragma unroll
    for (int kk = 0; kk < 2; kk++) {
      uint32_t ah[4], al[4];
      LDSM_X4(ah[0], ah[1], ah[2], ah[3], aA + kk * 32);
      LDSM_X4(al[0], al[1], al[2], al[3], aA + 5120 + kk * 32);
#pragma unroll
      for (int np = 0; np < 8; np++) {
        uint32_t bh[4], bl[4];
        uint32_t boff = (uint32_t)(kk * 4352 + np * 32);
        LDSM_X4T(bh[0], bh[1], bh[2], bh[3], aB + boff);
        LDSM_X4T(bl[0], bl[1], bl[2], bl[3], aB + 8704 + boff);
        mma_bf16(oacc[2 * np], ah, bh[0], bh[1]);
        mma_bf16(oacc[2 * np], ah, bl[0], bl[1]);
        mma_bf16(oacc[2 * np], al, bh[0], bh[1]);
        mma_bf16(oacc[2 * np + 1], ah, bh[2], bh[3]);
        mma_bf16(oacc[2 * np + 1], ah, bl[2], bl[3]);
        mma_bf16(oacc[2 * np + 1], al, bh[2], bh[3]);
      }
    }
    __syncthreads();
    if (c + 2 < 8) load_chunk(s, c + 2);
    CP_COMMIT();
  }

  // epilogue: split fragments to hi/lo packed words
  size_t row0 = (size_t)(rowbase + w * 16 + g) * 64;
  size_t row8 = row0 + 8 * 64;
#pragma unroll
  for (int np = 0; np < 8; np++) {
#pragma unroll
    for (int half = 0; half < 2; half++) {
      float* d = oacc[2 * np + half];
      int word = np * 8 + half * 4 + tig;
      float h0 = __bfloat162float(__float2bfloat16(d[0]));
      float h1 = __bfloat162float(__float2bfloat16(d[1]));
      float h2 = __bfloat162float(__float2bfloat16(d[2]));
      float h3 = __bfloat162float(__float2bfloat16(d[3]));
      Ph[row0 + word] = pack_bf(h0, h1);
      Pl[row0 + word] = pack_bf(d[0] - h0, d[1] - h1);
      Ph[row8 + word] = pack_bf(h2, h3);
      Pl[row8 + word] = pack_bf(d[2] - h2, d[3] - h3);
    }
  }
}

// ---------------------------------------------------------------------------
// Kernel B: fused attention. H fragments in registers (LDG prologue),
// 3-stage cp.async KV buffer, one __syncthreads per tile.
// Stage: Khi 0 / Klo 17408 / Vhi 34816 / Vlo 52224; 64 rows, stride 272.
// ---------------------------------------------------------------------------
#define TRS 272
#define STAGE 69632
#define SMEM_BYTES 208896           // 3 stages

__device__ __forceinline__ void load_kv_async(uint32_t sb, int s, int cb, int t) {
#pragma unroll
  for (int i = 0; i < 16; i++) {
    int idx = t + i * 256;                 // 0..4095
    int sec = idx >> 10, row = (idx >> 4) & 63, ch = idx & 15;
    const uint4* base = (sec == 0) ? gKh : (sec == 1) ? gKl : (sec == 2) ? gVh : gVl;
    cp16(sb + s * STAGE + sec * 17408 + row * TRS + ch * 16,
         base + (size_t)(cb + row) * 16 + ch);
  }
}

__global__ void __launch_bounds__(256, 1) attn_kernel(const int* __restrict__ adj) {
  extern __shared__ char smem[];
  uint32_t sb = smem_u32(smem);
  int t = threadIdx.x, w = t >> 5, lane = t & 31;
  int g = lane >> 2, tig = lane & 3;
  int rowbase = blockIdx.x * BM;
  int colstart = blockIdx.y * (NN / SPLITS);
  int q = lane >> 3, r = lane & 7;
  uint32_t offB = (uint32_t)(((q >> 1) * 8 + r) * TRS + (q & 1) * 16);
  uint32_t offV = (uint32_t)(34816 + ((q & 1) * 8 + r) * TRS + (q >> 1) * 16);

  // first two KV stages in flight
  load_kv_async(sb, 0, colstart, t);
  CP_COMMIT();
  load_kv_async(sb, 1, colstart + BN, t);
  CP_COMMIT();

  // H fragments via direct LDG (A-fragment layout == packed word layout)
  uint32_t ahf[8][4], alf[8][4];
  {
    const uint32_t* Hh = (const uint32_t*)gHh;
    const uint32_t* Hl = (const uint32_t*)gHl;
    size_t b0 = (size_t)(rowbase + w * 16 + g) * 64;
    size_t b8 = b0 + 8 * 64;
#pragma unroll
    for (int kk = 0; kk < 8; kk++) {
      int wd = kk * 8 + tig;
      ahf[kk][0] = Hh[b0 + wd];     ahf[kk][1] = Hh[b8 + wd];
      ahf[kk][2] = Hh[b0 + wd + 4]; ahf[kk][3] = Hh[b8 + wd + 4];
      alf[kk][0] = Hl[b0 + wd];     alf[kk][1] = Hl[b8 + wd];
      alf[kk][2] = Hl[b0 + wd + 4]; alf[kk][3] = Hl[b8 + wd + 4];
    }
  }

  float oacc[16][4];
#pragma unroll
  for (int c = 0; c < 16; c++)
#pragma unroll
    for (int k = 0; k < 4; k++) oacc[c][k] = 0.f;
  float den0 = 0.f, den1 = 0.f;

  const int* arow0 = adj + (size_t)(rowbase + w * 16 + g) * NN;
  const int* arow1 = arow0 + (size_t)8 * NN;

  int s3 = 0;
  for (int tt = 0; tt < TILES; tt++) {
    int cb = colstart + tt * BN;
    CP_WAIT1();
    __syncthreads();                        // L(tt) visible; stage (tt+2)%3 free
    if (tt + 2 < TILES) load_kv_async(sb, (tt + 2) % 3, colstart + (tt + 2) * BN, t);
    CP_COMMIT();

    // adj prefetch (hidden under S MMAs)
    int2 am[16];
#pragma unroll
    for (int n = 0; n < 8; n++) {
      am[n] = *(const int2*)(arow0 + cb + n * 8 + 2 * tig);
      am[n + 8] = *(const int2*)(arow1 + cb + n * 8 + 2 * tig);
    }

    uint32_t aBh = sb + (uint32_t)(s3 * STAGE) + offB;
    uint32_t aVh = sb + (uint32_t)(s3 * STAGE) + offV;

    // ---- S = H @ K^T (hi/lo: hh + hl + lh), A from registers ----
    float sacc[8][4];
#pragma unroll
    for (int c = 0; c < 8; c++)
#pragma unroll
      for (int k = 0; k < 4; k++) sacc[c][k] = 0.f;

#pragma unroll
    for (int kk = 0; kk < 8; kk++) {
#pragma unroll
      for (int np = 0; np < 4; np++) {
        uint32_t bh[4], bl[4];
        uint32_t boff = (uint32_t)(np * (16 * TRS) + kk * 32);
        LDSM_X4(bh[0], bh[1], bh[2], bh[3], aBh + boff);
        LDSM_X4(bl[0], bl[1], bl[2], bl[3], aBh + 17408 + boff);
        mma_bf16(sacc[2 * np], ahf[kk], bh[0], bh[1]);
        mma_bf16(sacc[2 * np], ahf[kk], bl[0], bl[1]);
        mma_bf16(sacc[2 * np], alf[kk], bh[0], bh[1]);
        mma_bf16(sacc[2 * np + 1], ahf[kk], bh[2], bh[3]);
        mma_bf16(sacc[2 * np + 1], ahf[kk], bl[2], bl[3]);
        mma_bf16(sacc[2 * np + 1], alf[kk], bh[2], bh[3]);
      }
    }

    // ---- leakyrelu + adj mask + exp -> P fragments -> PV ----
#pragma unroll
    for (int kk = 0; kk < 4; kk++) {
      uint32_t phi[4], plo[4];
#pragma unroll
      for (int cp = 0; cp < 2; cp++) {
        int n = 2 * kk + cp;
        int2 m0 = am[n];
        int2 m1 = am[n + 8];
        float e0 = sacc[n][0], e1 = sacc[n][1], e2 = sacc[n][2], e3 = sacc[n][3];
        e0 = e0 > 0.f ? e0 : ALPHA * e0;
        e1 = e1 > 0.f ? e1 : ALPHA * e1;
        e2 = e2 > 0.f ? e2 : ALPHA * e2;
        e3 = e3 > 0.f ? e3 : ALPHA * e3;
        float p0 = (m0.x > 0) ? __expf(e0) : 0.f;
        float p1 = (m0.y > 0) ? __expf(e1) : 0.f;
        float p2 = (m1.x > 0) ? __expf(e2) : 0.f;
        float p3 = (m1.y > 0) ? __expf(e3) : 0.f;
        den0 += p0 + p1;
        den1 += p2 + p3;
        float h0 = __bfloat162float(__float2bfloat16(p0));
        float h1 = __bfloat162float(__float2bfloat16(p1));
        float h2 = __bfloat162float(__float2bfloat16(p2));
        float h3 = __bfloat162float(__float2bfloat16(p3));
        phi[2 * cp + 0] = pack_bf(h0, h1);
        phi[2 * cp + 1] = pack_bf(h2, h3);
        plo[2 * cp + 0] = pack_bf(p0 - h0, p1 - h1);
        plo[2 * cp + 1] = pack_bf(p2 - h2, p3 - h3);
      }
#pragma unroll
      for (int cp = 0; cp < 8; cp++) {
        uint32_t vh[4], vl[4];
        uint32_t voff = (uint32_t)(kk * (16 * TRS) + cp * 32);
        LDSM_X4T(vh[0], vh[1], vh[2], vh[3], aVh + voff);
        LDSM_X4T(vl[0], vl[1], vl[2], vl[3], aVh + 17408 + voff);
        mma_bf16(oacc[2 * cp], phi, vh[0], vh[1]);
        mma_bf16(oacc[2 * cp], phi, vl[0], vl[1]);
        mma_bf16(oacc[2 * cp], plo, vh[0], vh[1]);
        mma_bf16(oacc[2 * cp + 1], phi, vh[2], vh[3]);
        mma_bf16(oacc[2 * cp + 1], phi, vl[2], vl[3]);
        mma_bf16(oacc[2 * cp + 1], plo, vh[2], vh[3]);
      }
    }
    s3 = (s3 == 2) ? 0 : s3 + 1;
  }

  // ---- epilogue: den (quad reduce) + O partials ----
  den0 += __shfl_xor_sync(0xffffffffu, den0, 1);
  den0 += __shfl_xor_sync(0xffffffffu, den0, 2);
  den1 += __shfl_xor_sync(0xffffffffu, den1, 1);
  den1 += __shfl_xor_sync(0xffffffffu, den1, 2);
  if (tig == 0) {
    gDen[(size_t)blockIdx.y * NN + rowbase + w * 16 + g] = den0;
    gDen[(size_t)blockIdx.y * NN + rowbase + w * 16 + g + 8] = den1;
  }
  float* base0 = gNum + ((size_t)blockIdx.y * NN + rowbase + w * 16 + g) * DD;
  float* base1 = base0 + (size_t)8 * DD;
#pragma unroll
  for (int c = 0; c < 16; c++) {
    *(float2*)(base0 + c * 8 + 2 * tig) = make_float2(oacc[c][0], oacc[c][1]);
    *(float2*)(base1 + c * 8 + 2 * tig) = make_float2(oacc[c][2], oacc[c][3]);
  }
}

// ---------------------------------------------------------------------------
// Kernel C: combine split partials, divide, ELU (float4 vectorized).
// ---------------------------------------------------------------------------
__global__ __launch_bounds__(256) void reduce_kernel(float* __restrict__ out) {
  int idx = blockIdx.x * 256 + threadIdx.x;   // over N*D/4 = 262144
  int row = idx >> 5;
  int c4 = (idx & 31) * 4;
  float4 num = make_float4(0.f, 0.f, 0.f, 0.f);
  float den = 0.f;
#pragma unroll
  for (int s = 0; s < SPLITS; s++) {
    float4 v = *(const float4*)(gNum + ((size_t)s * NN + row) * DD + c4);
    num.x += v.x; num.y += v.y; num.z += v.z; num.w += v.w;
    den += gDen[(size_t)s * NN + row];
  }
  float inv = 1.f / den;
  float h0 = num.x * inv, h1 = num.y * inv, h2 = num.z * inv, h3 = num.w * inv;
  float4 o;
  o.x = (h0 > 0.f) ? h0 : expm1f(h0);
  o.y = (h1 > 0.f) ? h1 : expm1f(h1);
  o.z = (h2 > 0.f) ? h2 : expm1f(h2);
  o.w = (h3 > 0.f) ? h3 : expm1f(h3);
  *(float4*)(out + (size_t)row * DD + c4) = o;
}

// ---------------------------------------------------------------------------
extern "C" void kernel_launch(void* const* d_in, const int* in_sizes, int n_in,
                              void* d_out, int out_size) {
  const float* inp = (const float*)d_in[0];
  const int* adj = (const int*)d_in[1];
  const float* W = (const float*)d_in[2];
  const float* W2 = (const float*)d_in[3];
  const float* W3 = (const float*)d_in[4];
  float* out = (float*)d_out;

  split_kernel<<<4288, 256>>>(inp, W, W2, W3);

  cudaFuncSetAttribute(proj_kernel, cudaFuncAttributeMaxDynamicSharedMemorySize,
                       PSMEM);
  proj_kernel<<<dim3(NN / 64, 3), 128, PSMEM>>>();

  cudaFuncSetAttribute(attn_kernel, cudaFuncAttributeMaxDynamicSharedMemorySize,
                       SMEM_BYTES);
  attn_kernel<<<dim3(NN / BM, SPLITS), 256, SMEM_BYTES>>>(adj);

  reduce_kernel<<<(NN * DD) / 1024, 256>>>(out);
}